// round 17
// baseline (speedup 1.0000x reference)
#include <cuda_runtime.h>
#include <cuda_bf16.h>
#include <math.h>

#define NSAMP 64
#define TLEN  512
#define DDIM  16
#define NDIAG 1023
#define BIGL  1.0e10f
#define LOG2E 1.4426950408889634f
#define LN2   0.6931471805599453f
#define NPHASE 135   // 8 global warps, lag 8: gw=7 reaches diag 1022 at phase 134

__device__ float g_res[NSAMP];

typedef unsigned long long ull;

__device__ __forceinline__ float ex2f(float x){ float y; asm("ex2.approx.ftz.f32 %0, %1;" : "=f"(y) : "f"(x)); return y; }
__device__ __forceinline__ float lg2f(float x){ float y; asm("lg2.approx.ftz.f32 %0, %1;" : "=f"(y) : "f"(x)); return y; }
__device__ __forceinline__ ull mul2(ull a, ull b){ ull d; asm("mul.rn.f32x2 %0, %1, %2;" : "=l"(d) : "l"(a), "l"(b)); return d; }
__device__ __forceinline__ ull add2(ull a, ull b){ ull d; asm("add.rn.f32x2 %0, %1, %2;" : "=l"(d) : "l"(a), "l"(b)); return d; }
__device__ __forceinline__ ull fma2(ull a, ull b, ull c){ ull d; asm("fma.rn.f32x2 %0, %1, %2, %3;" : "=l"(d) : "l"(a), "l"(b), "l"(c)); return d; }
#define UNPK(LO, HI, P) asm("mov.b64 {%0, %1}, %2;" : "=f"(LO), "=f"(HI) : "l"(P))
#define PK(P, LO, HI)   asm("mov.b64 %0, {%1, %2};" : "=l"(P) : "f"(LO), "f"(HI))

// Z permutation for 2-cell threads (R12/R13-proven): row z -> slot
// (z>>1) + 256*(z&1); threads 2 rows apart hit consecutive slots; 18-float
// pitch => conflict-free.
#define ZSLOT(z) (((z) >> 1) + 256 * ((z) & 1))

// Self-tagged mailbox poll: slot idx holds (value<<32)|tag, tag==idx when ready.
__device__ __forceinline__ float mbox_poll(unsigned mb32, int idx) {
    ull pk; const unsigned a = mb32 + (unsigned)idx * 8u;
    do {
        asm volatile("ld.volatile.shared.b64 %0, [%1];" : "=l"(pk) : "r"(a) : "memory");
    } while ((unsigned)pk != (unsigned)idx);
    return __uint_as_float((unsigned)(pk >> 32));
}

// ---------------------------------------------------------------------------
// FUSED soft-DTW, 2-CTA cluster per sample (halves per-SMSP fma-pipe work —
// the measured bottleneck). CTA rank r owns rows [256r, 256r+256); 128
// threads = 4 warps (1/SMSP), 2 cells/thread. Global staircase lag 8 over 8
// warps. Cross-CTA boundary: CTA0-w3-lane31 fire-and-forget remote-stores
// (value,tag) u64 into CTA1's 1024-slot mailbox (covers the whole run: no
// wrap, no back-pressure, NO fences); CTA1-w0-lane0 polls the self-tagged
// slot (arrives ~1 phase early, so first-try hit).
// ---------------------------------------------------------------------------
__global__ void __launch_bounds__(128) __cluster_dims__(2, 1, 1)
fused_dp_kernel(const float* __restrict__ X, const float* __restrict__ Z)
{
    __shared__ float zsm[512 * 18];    // permuted Z rows: 16 data + z2*log2e + pad
    __shared__ float rings[5][32];     // in-CTA: warp w reads rings[w], writes rings[w+1]
    __shared__ ull   mbox[1024];       // CTA1: incoming boundary values (self-tagged)

    const int tid  = threadIdx.x;
    const int w    = tid >> 5;
    const int lane = tid & 31;
    unsigned rank;
    asm("mov.u32 %0, %%cluster_ctarank;" : "=r"(rank));
    const int  n       = blockIdx.x >> 1;
    const int  gw      = (int)rank * 4 + w;          // global staircase warp id
    const int  row0    = (int)rank * 256 + 2 * tid;  // first of this thread's 2 rows
    const bool edge    = (rank == 0 && w == 3);      // remote-writes row 255
    const bool useMbox = (rank == 1 && w == 0);      // reads row-255 boundary

    // ---- stage Z into permuted smem (+ z2*log2e at offset 16) ----
    for (int r = tid; r < 512; r += 128) {
        const float* zg = Z + r * 16;
        float vals[16]; float s2 = 0.f;
        #pragma unroll
        for (int k = 0; k < 16; k++) { float v = zg[k]; vals[k] = v; s2 = fmaf(v, v, s2); }
        float* dst = zsm + ZSLOT(r) * 18;
        #pragma unroll
        for (int k = 0; k < 16; k++) dst[k] = vals[k];
        dst[16] = s2 * LOG2E;
    }
    for (int i = tid; i < 5 * 32; i += 128) (&rings[0][0])[i] = BIGL;
    #pragma unroll
    for (int i = 0; i < 8; i++) mbox[tid + 128 * i] = 0xFFFFFFFFull;  // never-match tags

    // ---- stage this thread's 2 X rows, pre-scaled by -2*log2e ----
    ull xp[2][8]; float x2L[2];
    {
        const ull* Xp = (const ull*)(X + ((size_t)n * TLEN + row0) * DDIM);
        #pragma unroll
        for (int c = 0; c < 2; c++) {
            float s2 = 0.f;
            #pragma unroll
            for (int k = 0; k < 8; k++) {
                ull p = Xp[c * 8 + k];
                float lo, hi; UNPK(lo, hi, p);
                s2 = fmaf(lo, lo, fmaf(hi, hi, s2));
                lo *= -2.0f * LOG2E; hi *= -2.0f * LOG2E;
                PK(xp[c][k], lo, hi);
            }
            x2L[c] = s2 * LOG2E;
        }
    }

    float rc0 = BIGL, rc1 = BIGL, rd0 = BIGL, rd1 = BIGL;
    if (rank == 0 && tid == 0) rd0 = 0.0f;           // corner R[0][0]
    float resv = BIGL;

    float* ringr = &rings[w][0];                     // CTA0-w0 reads BIGL row
    float* ringw = &rings[w + 1][0];

    const unsigned lmbox = (unsigned)__cvta_generic_to_shared(&mbox[0]);
    unsigned r_mbox;                                  // CTA1's mailbox, from CTA0
    asm("mapa.shared::cluster.u32 %0, %1, %2;" : "=r"(r_mbox) : "r"(lmbox), "r"(rank ^ 1u));

    __syncthreads();
    asm volatile("barrier.cluster.arrive.aligned;" ::: "memory");  // mbox init visible
    asm volatile("barrier.cluster.wait.aligned;" ::: "memory");

    ull   zr[2][8];     // 2-row Z cache; slot(z) = (z+row0)&1 (kstart even)
    float z2c[2];
    float dD[2][2];     // D ping-pong: dD[J&1][cell]

#define ZLOAD(SLOT, JUC)                                                       \
    {                                                                          \
        int jc = (JUC); jc = jc < 0 ? 0 : (jc > 511 ? 511 : jc);               \
        const ull* zp = (const ull*)(zsm + ZSLOT(jc) * 18);                    \
        zr[SLOT][0] = zp[0]; zr[SLOT][1] = zp[1];                              \
        zr[SLOT][2] = zp[2]; zr[SLOT][3] = zp[3];                              \
        zr[SLOT][4] = zp[4]; zr[SLOT][5] = zp[5];                              \
        zr[SLOT][6] = zp[6]; zr[SLOT][7] = zp[7];                              \
        z2c[SLOT] = ((const float*)zp)[16];                                    \
    }

#define DCOMP(DST, C, SLOT)                                                    \
    {                                                                          \
        ull a0 = mul2(xp[C][0], zr[SLOT][0]);                                  \
        ull a1 = mul2(xp[C][1], zr[SLOT][1]);                                  \
        a0 = fma2(xp[C][2], zr[SLOT][2], a0);                                  \
        a1 = fma2(xp[C][3], zr[SLOT][3], a1);                                  \
        a0 = fma2(xp[C][4], zr[SLOT][4], a0);                                  \
        a1 = fma2(xp[C][5], zr[SLOT][5], a1);                                  \
        a0 = fma2(xp[C][6], zr[SLOT][6], a0);                                  \
        a1 = fma2(xp[C][7], zr[SLOT][7], a1);                                  \
        a0 = add2(a0, a1);                                                     \
        float lo, hi; UNPK(lo, hi, a0);                                        \
        (DST) = (lo + hi) + (x2L[C] + z2c[SLOT]);                              \
    }

    // ---- prologue (R13-proven slot algebra): prime cache + dD[0] ----
    const int kstart = -8 * gw;
    ZLOAD(1, kstart - row0 - 1)
    ZLOAD(0, kstart - row0)
    DCOMP(dD[0][0], 0, 0)
    DCOMP(dD[0][1], 1, 1)
    ZLOAD(1, kstart - row0 + 1)

#define DP_STEP(J)                                                             \
    {                                                                          \
        const int cur = kwb + (J);                                             \
        float bval;                                                            \
        if (useMbox) {                         /* warp-uniform branch */      \
            bval = BIGL;                                                       \
            if (lane == 0 && (unsigned)(cur - 1) < 1023u)                      \
                bval = mbox_poll(lmbox, cur - 1);                              \
        } else {                                                               \
            bval = ringr[(cur - 1) & 31];                                      \
        }                                                                      \
        float upsh = __shfl_up_sync(0xffffffffu, rc1, 1);                      \
        const float u0 = (lane == 0) ? bval : upsh;                            \
        const float u1 = rc0;                                                  \
        {                                                                      \
            float m  = fminf(fminf(u0, rc0), rd0);                             \
            float Mx = fmaxf(fmaxf(u0, rc0), rd0);                             \
            float mid = ((u0 + rc0) + rd0) - m - Mx;                           \
            float s  = 1.0f + ex2f(m - mid) + ex2f(m - Mx);                    \
            rd0 = u0; rc0 = (dD[(J) & 1][0] + m) - lg2f(s);                    \
        }                                                                      \
        {                                                                      \
            float m  = fminf(fminf(u1, rc1), rd1);                             \
            float Mx = fmaxf(fmaxf(u1, rc1), rd1);                             \
            float mid = ((u1 + rc1) + rd1) - m - Mx;                           \
            float s  = 1.0f + ex2f(m - mid) + ex2f(m - Mx);                    \
            rd1 = u1; rc1 = (dD[(J) & 1][1] + m) - lg2f(s);                    \
        }                                                                      \
        if (cur == NDIAG - 1) resv = rc1;                                      \
        if (lane == 31) {                                                      \
            ringw[cur & 31] = rc1;                                             \
            if (edge && (unsigned)cur < 1023u) {                               \
                ull pk = ((ull)__float_as_uint(rc1) << 32) | (unsigned)cur;    \
                asm volatile("st.shared::cluster.b64 [%0], %1;"                \
                    :: "r"(r_mbox + (unsigned)cur * 8u), "l"(pk) : "memory");  \
            }                                                                  \
        }                                                                      \
        /* fused: D for diag cur+1 (cell1 reads slot J&1 BEFORE ZLOAD) */      \
        DCOMP(dD[((J) + 1) & 1][0], 0, ((J) + 1) & 1)                          \
        DCOMP(dD[((J) + 1) & 1][1], 1, ((J) + 0) & 1)                          \
        ZLOAD((J) & 1, cur + 2 - row0)                                         \
    }

    #pragma unroll 1
    for (int p = 0; p < NPHASE; ++p) {
        const int kwb = 8 * p - 8 * gw;
        DP_STEP(0) DP_STEP(1) DP_STEP(2) DP_STEP(3)
        DP_STEP(4) DP_STEP(5) DP_STEP(6) DP_STEP(7)
        __syncthreads();
    }
#undef DP_STEP
#undef DCOMP
#undef ZLOAD

    if (rank == 1 && tid == 127) g_res[n] = resv * LN2;   // row 511: R[T,T]

    asm volatile("barrier.cluster.arrive.aligned;" ::: "memory");
    asm volatile("barrier.cluster.wait.aligned;" ::: "memory");
}

// ---------------------------------------------------------------------------
// Deterministic weighted reduction.
// ---------------------------------------------------------------------------
__global__ void reduce_kernel(const float* __restrict__ wts, float* __restrict__ out)
{
    __shared__ float s[64];
    const int tid = threadIdx.x;
    s[tid] = g_res[tid] * wts[tid];
    __syncthreads();
    #pragma unroll
    for (int off = 32; off > 0; off >>= 1) {
        if (tid < off) s[tid] += s[tid + off];
        __syncthreads();
    }
    if (tid == 0) out[0] = s[0];
}

// ---------------------------------------------------------------------------
extern "C" void kernel_launch(void* const* d_in, const int* in_sizes, int n_in,
                              void* d_out, int out_size)
{
    const float* X = nullptr; const float* wts = nullptr; const float* Z = nullptr;
    for (int i = 0; i < n_in; i++) {
        if      (in_sizes[i] == NSAMP)        wts = (const float*)d_in[i];
        else if (in_sizes[i] == TLEN * DDIM)  Z   = (const float*)d_in[i];
        else                                  X   = (const float*)d_in[i];
    }
    float* out = (float*)d_out;

    fused_dp_kernel<<<2 * NSAMP, 128>>>(X, Z);   // 64 clusters of 2 CTAs
    reduce_kernel<<<1, 64>>>(wts, out);
}